// round 14
// baseline (speedup 1.0000x reference)
#include <cuda_runtime.h>
#include <cuda_bf16.h>

// PointMatcher: pred (N,20,2) f32, gt (M,20,2) f32.
// out = [ matched_points (N*40) | confidence (N) | indices-as-float (N) ]
//
// R13: split-M two-stage, TI=2 with NEGATED pred in registers (inner-loop LDS
// 50 -> 10 per thread-tile), SPLIT=8 (4096 blocks, 4 CTAs/SM via launch
// bounds), f32x2 packed math, parallel stage2 (one thread per row-chunk).

#define P_PTS    20
#define NPAIR    10
#define NQ2      5                // pair-of-pairs
#define ROW_F    40
#define TI       2                // preds per block
#define TILE_J   128              // gt rows per tile = NTHREADS
#define NTHREADS 128
#define SPLIT    8

typedef unsigned long long u64;

#define MAXN 4096
__device__ float g_pmin[MAXN * SPLIT];
__device__ int   g_pidx[MAXN * SPLIT];

__device__ __forceinline__ u64 pack2(float lo, float hi) {
    u64 r; asm("mov.b64 %0, {%1, %2};" : "=l"(r) : "f"(lo), "f"(hi)); return r;
}
__device__ __forceinline__ void unpack2(u64 v, float& lo, float& hi) {
    asm("mov.b64 {%0, %1}, %2;" : "=f"(lo), "=f"(hi) : "l"(v));
}
__device__ __forceinline__ u64 add2(u64 a, u64 b) {
    u64 r; asm("add.rn.f32x2 %0, %1, %2;" : "=l"(r) : "l"(a), "l"(b)); return r;
}
__device__ __forceinline__ u64 mul2(u64 a, u64 b) {
    u64 r; asm("mul.rn.f32x2 %0, %1, %2;" : "=l"(r) : "l"(a), "l"(b)); return r;
}
__device__ __forceinline__ u64 fma2(u64 a, u64 b, u64 c) {
    u64 r; asm("fma.rn.f32x2 %0, %1, %2, %3;" : "=l"(r) : "l"(a), "l"(b), "l"(c)); return r;
}
__device__ __forceinline__ float fsqrt_approx(float x) {
    float r; asm("sqrt.approx.f32 %0, %1;" : "=f"(r) : "f"(x)); return r;
}

// ---------------- Stage 1: partial min/argmin ----------------
__global__ __launch_bounds__(NTHREADS, 4)
void PointMatcher_stage1(const float* __restrict__ pred,
                         const float* __restrict__ gt,
                         int N, int M)
{
    // gt tile, transposed, pairs-of-pairs for LDS.128 (NOT negated; pred is)
    __shared__ u64 tX[NQ2][TILE_J][2];
    __shared__ u64 tY[NQ2][TILE_J][2];
    __shared__ float red_m[TI][NTHREADS / 32];
    __shared__ int   red_i[TI][NTHREADS / 32];

    const int tid   = threadIdx.x;
    const int lane  = tid & 31;
    const int warp  = tid >> 5;
    const int i0    = blockIdx.x * TI;
    const int split = blockIdx.y;

    const int chunk  = (M + SPLIT - 1) / SPLIT;
    const int jStart = split * chunk;
    const int jEnd   = min(jStart + chunk, M);

    // ---- TI pred rows, NEGATED, packed into registers ----
    u64 pX[TI][NPAIR], pY[TI][NPAIR];
    #pragma unroll
    for (int i = 0; i < TI; i++) {
        int row = i0 + i;
        if (row >= N) row = N - 1;
        const float4* p4 = reinterpret_cast<const float4*>(pred + (size_t)row * ROW_F);
        #pragma unroll
        for (int q = 0; q < NPAIR; q++) {
            float4 v = __ldg(p4 + q);
            pX[i][q] = pack2(-v.x, -v.z);
            pY[i][q] = pack2(-v.y, -v.w);
        }
    }

    float mn[TI];
    int   mi[TI];
    #pragma unroll
    for (int i = 0; i < TI; i++) { mn[i] = 3.4e38f; mi[i] = jStart; }

    for (int jBase = jStart; jBase < jEnd; jBase += TILE_J) {
        __syncthreads();

        // ---- stage gt tile: [q2][j][q&1], packed (no negate) ----
        {
            const float4* g4 = reinterpret_cast<const float4*>(gt + (size_t)jBase * ROW_F);
            #pragma unroll
            for (int k = 0; k < (TILE_J * NPAIR) / NTHREADS; k++) {
                int lin4 = tid + k * NTHREADS;       // [0, TILE_J*10)
                int jl   = lin4 / NPAIR;
                int q    = lin4 % NPAIR;
                float4 v = make_float4(1e30f, 1e30f, 1e30f, 1e30f);
                if (jBase + jl < M) v = __ldg(g4 + lin4);
                tX[q >> 1][jl][q & 1] = pack2(v.x, v.z);
                tY[q >> 1][jl][q & 1] = pack2(v.y, v.w);
            }
        }
        __syncthreads();

        const int jg = jBase + tid;
        if (jg < jEnd) {
            float s0[TI], s1[TI];
            #pragma unroll
            for (int i = 0; i < TI; i++) { s0[i] = 0.0f; s1[i] = 0.0f; }

            #pragma unroll
            for (int q2 = 0; q2 < NQ2; q2++) {
                // LDS.128: two x-pairs and two y-pairs of this gt row
                ulonglong2 gx = *reinterpret_cast<const ulonglong2*>(&tX[q2][tid][0]);
                ulonglong2 gy = *reinterpret_cast<const ulonglong2*>(&tY[q2][tid][0]);
                #pragma unroll
                for (int i = 0; i < TI; i++) {
                    u64 dxa = add2(pX[i][2 * q2 + 0], gx.x);   // gt + (-pred)
                    u64 dya = add2(pY[i][2 * q2 + 0], gy.x);
                    u64 dxb = add2(pX[i][2 * q2 + 1], gx.y);
                    u64 dyb = add2(pY[i][2 * q2 + 1], gy.y);
                    u64 d2a = fma2(dya, dya, mul2(dxa, dxa));
                    u64 d2b = fma2(dyb, dyb, mul2(dxb, dxb));
                    float a0, a1, b0, b1;
                    unpack2(d2a, a0, a1);
                    unpack2(d2b, b0, b1);
                    s0[i] += fsqrt_approx(a0) + fsqrt_approx(b0);
                    s1[i] += fsqrt_approx(a1) + fsqrt_approx(b1);
                }
            }
            #pragma unroll
            for (int i = 0; i < TI; i++) {
                float d = (s0[i] + s1[i]) * (1.0f / P_PTS);
                if (d < mn[i]) { mn[i] = d; mi[i] = jg; }
            }
        }
    }
    __syncthreads();

    // ---- block reduction: min+argmin (tie -> lower index) ----
    #pragma unroll
    for (int i = 0; i < TI; i++) {
        float m = mn[i];
        int   j = mi[i];
        #pragma unroll
        for (int off = 16; off > 0; off >>= 1) {
            float m2 = __shfl_down_sync(0xFFFFFFFFu, m, off);
            int   j2 = __shfl_down_sync(0xFFFFFFFFu, j, off);
            if (m2 < m || (m2 == m && j2 < j)) { m = m2; j = j2; }
        }
        if (lane == 0) { red_m[i][warp] = m; red_i[i][warp] = j; }
    }
    __syncthreads();

    if (tid < TI) {
        float m = red_m[tid][0];
        int   j = red_i[tid][0];
        #pragma unroll
        for (int w = 1; w < NTHREADS / 32; w++) {
            float m2 = red_m[tid][w];
            int   j2 = red_i[tid][w];
            if (m2 < m || (m2 == m && j2 < j)) { m = m2; j = j2; }
        }
        int row = i0 + tid;
        if (row < N) {
            g_pmin[(size_t)row * SPLIT + split] = m;
            g_pidx[(size_t)row * SPLIT + split] = j;
        }
    }
}

// ---------------- Stage 2: reduce partials, gather, outputs ----------------
// One thread per (row, float4-chunk): N*10 threads.
__global__ __launch_bounds__(256)
void PointMatcher_stage2(const float* __restrict__ gt,
                         float* __restrict__ out,
                         int N, int M)
{
    int idx = blockIdx.x * blockDim.x + threadIdx.x;
    int row = idx / (ROW_F / 4);
    int k   = idx % (ROW_F / 4);
    if (row >= N) return;

    // splits cover increasing j ranges; strict < keeps lowest j on ties
    float m = g_pmin[(size_t)row * SPLIT + 0];
    int   j = g_pidx[(size_t)row * SPLIT + 0];
    #pragma unroll
    for (int s = 1; s < SPLIT; s++) {
        float m2 = g_pmin[(size_t)row * SPLIT + s];
        int   j2 = g_pidx[(size_t)row * SPLIT + s];
        if (m2 < m) { m = m2; j = j2; }
    }

    // gather one float4 of the matched gt row
    const float4* src = reinterpret_cast<const float4*>(gt + (size_t)j * ROW_F);
    float4*       dst = reinterpret_cast<float4*>(out + (size_t)row * ROW_F);
    dst[k] = __ldg(src + k);

    if (k == 0) {
        float conf = (m > 2.0f) ? 0.0f : __expf(-m);
        out[(size_t)N * ROW_F + row]     = conf;          // confidence
        out[(size_t)N * ROW_F + N + row] = (float)j;      // index as float
    }
}

extern "C" void kernel_launch(void* const* d_in, const int* in_sizes, int n_in,
                              void* d_out, int out_size) {
    const float* pred = (const float*)d_in[0];
    const float* gt   = (const float*)d_in[1];
    float*       out  = (float*)d_out;

    const int N = in_sizes[0] / ROW_F;   // 1024
    const int M = in_sizes[1] / ROW_F;   // 2048

    dim3 grid1((N + TI - 1) / TI, SPLIT);
    PointMatcher_stage1<<<grid1, NTHREADS>>>(pred, gt, N, M);

    const int blocks2 = (N * (ROW_F / 4) + 255) / 256;
    PointMatcher_stage2<<<blocks2, 256>>>(gt, out, N, M);
}

// round 16
// speedup vs baseline: 2.2261x; 2.2261x over previous
#include <cuda_runtime.h>
#include <cuda_bf16.h>

// PointMatcher: pred (N,20,2) f32, gt (M,20,2) f32.
// out = [ matched_points (N*40) | confidence (N) | indices-as-float (N) ]
//
// R15: thread-per-pred design. No smem, no transpose, no syncs in stage1.
// Each thread holds its (negated, f32x2-packed) pred row in registers and
// scans a contiguous gt chunk with warp-uniform __ldg (broadcast, L1-hot).
// Partial results packed as u64 (dist_bits<<32)|j -> integer min == (dist,
// then lowest j). Stage2: warp per row, shfl-min over 64 partials + gather.

#define P_PTS    20
#define NPAIR    10
#define ROW_F    40
#define NT1      128
#define SPLIT    64
#define MAXN     4096

typedef unsigned long long u64;
typedef unsigned int u32;

__device__ u64 g_part[(size_t)MAXN * SPLIT];

__device__ __forceinline__ u64 pack2(float lo, float hi) {
    u64 r; asm("mov.b64 %0, {%1, %2};" : "=l"(r) : "f"(lo), "f"(hi)); return r;
}
__device__ __forceinline__ void unpack2(u64 v, float& lo, float& hi) {
    asm("mov.b64 {%0, %1}, %2;" : "=f"(lo), "=f"(hi) : "l"(v));
}
__device__ __forceinline__ u64 add2(u64 a, u64 b) {
    u64 r; asm("add.rn.f32x2 %0, %1, %2;" : "=l"(r) : "l"(a), "l"(b)); return r;
}
__device__ __forceinline__ u64 mul2(u64 a, u64 b) {
    u64 r; asm("mul.rn.f32x2 %0, %1, %2;" : "=l"(r) : "l"(a), "l"(b)); return r;
}
__device__ __forceinline__ u64 fma2(u64 a, u64 b, u64 c) {
    u64 r; asm("fma.rn.f32x2 %0, %1, %2, %3;" : "=l"(r) : "l"(a), "l"(b), "l"(c)); return r;
}
__device__ __forceinline__ float fsqrt_approx(float x) {
    float r; asm("sqrt.approx.f32 %0, %1;" : "=f"(r) : "f"(x)); return r;
}
__device__ __forceinline__ u64 umin64(u64 a, u64 b) { return a < b ? a : b; }

// ---------------- Stage 1: thread-per-pred partial min/argmin ----------------
__global__ __launch_bounds__(NT1, 4)
void PointMatcher_stage1(const float* __restrict__ pred,
                         const float* __restrict__ gt,
                         int N, int M)
{
    const int row   = blockIdx.x * NT1 + threadIdx.x;
    const int split = blockIdx.y;
    const int chunk  = (M + SPLIT - 1) / SPLIT;
    const int jStart = split * chunk;
    const int jEnd   = min(jStart + chunk, M);

    const bool valid = (row < N);
    const int  prow  = valid ? row : (N > 0 ? N - 1 : 0);

    // pred row, NEGATED, packed pairs, in registers
    u64 pX[NPAIR], pY[NPAIR];
    {
        const float4* p4 = reinterpret_cast<const float4*>(pred + (size_t)prow * ROW_F);
        #pragma unroll
        for (int q = 0; q < NPAIR; q++) {
            float4 v = __ldg(p4 + q);
            pX[q] = pack2(-v.x, -v.z);
            pY[q] = pack2(-v.y, -v.w);
        }
    }

    float mn = 3.4e38f;
    int   mj = jStart;

    const float4* g4base = reinterpret_cast<const float4*>(gt);
    for (int j = jStart; j < jEnd; j++) {
        const float4* g4 = g4base + (size_t)j * NPAIR;   // warp-uniform address
        float s0 = 0.0f, s1 = 0.0f, s2 = 0.0f, s3 = 0.0f;
        #pragma unroll
        for (int q = 0; q < NPAIR; q++) {
            float4 v = __ldg(g4 + q);                    // broadcast, L1-hot
            u64 gx = pack2(v.x, v.z);
            u64 gy = pack2(v.y, v.w);
            u64 dx = add2(pX[q], gx);                    // gt - pred
            u64 dy = add2(pY[q], gy);
            u64 d2 = fma2(dy, dy, mul2(dx, dx));
            float lo, hi;
            unpack2(d2, lo, hi);
            if (q & 1) { s2 += fsqrt_approx(lo); s3 += fsqrt_approx(hi); }
            else       { s0 += fsqrt_approx(lo); s1 += fsqrt_approx(hi); }
        }
        float d = ((s0 + s1) + (s2 + s3)) * (1.0f / P_PTS);
        if (d < mn) { mn = d; mj = j; }                  // strict < -> lowest j
    }

    if (valid) {
        u64 key = ((u64)__float_as_uint(mn) << 32) | (u32)mj;
        g_part[(size_t)row * SPLIT + split] = key;       // every slot written
    }
}

// ---------------- Stage 2: warp per row — reduce 64 partials, gather ----------------
__global__ __launch_bounds__(256)
void PointMatcher_stage2(const float* __restrict__ gt,
                         float* __restrict__ out,
                         int N)
{
    const int gwarp = (blockIdx.x * 256 + threadIdx.x) >> 5;
    const int lane  = threadIdx.x & 31;
    if (gwarp >= N) return;
    const int row = gwarp;

    u64 k0 = g_part[(size_t)row * SPLIT + lane];
    u64 k1 = g_part[(size_t)row * SPLIT + 32 + lane];
    u64 k  = umin64(k0, k1);
    #pragma unroll
    for (int off = 16; off > 0; off >>= 1)
        k = umin64(k, __shfl_down_sync(0xFFFFFFFFu, k, off));
    k = __shfl_sync(0xFFFFFFFFu, k, 0);

    const int   j = (int)(u32)(k & 0xFFFFFFFFu);
    const float m = __uint_as_float((u32)(k >> 32));

    if (lane < NPAIR) {
        float4 v = __ldg(reinterpret_cast<const float4*>(gt + (size_t)j * ROW_F) + lane);
        reinterpret_cast<float4*>(out + (size_t)row * ROW_F)[lane] = v;
    } else if (lane == 10) {
        out[(size_t)N * ROW_F + row] = (m > 2.0f) ? 0.0f : __expf(-m);
    } else if (lane == 11) {
        out[(size_t)N * ROW_F + N + row] = (float)j;
    }
}

extern "C" void kernel_launch(void* const* d_in, const int* in_sizes, int n_in,
                              void* d_out, int out_size) {
    const float* pred = (const float*)d_in[0];
    const float* gt   = (const float*)d_in[1];
    float*       out  = (float*)d_out;

    const int N = in_sizes[0] / ROW_F;   // 1024
    const int M = in_sizes[1] / ROW_F;   // 2048

    dim3 grid1((N + NT1 - 1) / NT1, SPLIT);
    PointMatcher_stage1<<<grid1, NT1>>>(pred, gt, N, M);

    const int warps2  = N;                       // one warp per row
    const int blocks2 = (warps2 * 32 + 255) / 256;
    PointMatcher_stage2<<<blocks2, 256>>>(gt, out, N);
}